// round 1
// baseline (speedup 1.0000x reference)
#include <cuda_runtime.h>

// Problem constants
#define BB    8
#define C     128
#define W     256
#define H     256
#define NPIX  (W*H)          // 65536 pixels per image
#define K     2

// Output buffer layout (concatenated f32, raw reshapes):
//  [0,256)                              centersIterout [2,128]
//  [256, 256+BB*NPIX)                   labelsout      [8,1,256,256]
//  [.., +BB*2*NPIX)                     labels_onehot  [8,2,256,256]  (raw reshape of [b,N,2] -> interleaved pairs)
//  [.., +BB*2*NPIX)                     dist2center    [8,2,256,256]  (raw reshape -> interleaved pairs)
//  [.., +BB*NPIX)                       labelTinit     (== labelsout)
#define OFF_CENTERS 0
#define OFF_LABELS  256
#define OFF_ONEHOT  (OFF_LABELS + BB*NPIX)
#define OFF_DIST    (OFF_ONEHOT + BB*2*NPIX)
#define OFF_LABELT  (OFF_DIST   + BB*2*NPIX)

// Scratch (no allocations allowed -> __device__ globals)
__device__ float g_sum[2*C];   // per-label channel sums for batch 7: [k*128+ch]
__device__ int   g_count1;     // count of label==1 pixels in batch 7

// ---------------------------------------------------------------------------
// Kernel 0: zero scratch (graph replays re-run everything, must reset)
// ---------------------------------------------------------------------------
__global__ void k_zero() {
    int t = threadIdx.x;
    if (t < 2*C) g_sum[t] = 0.0f;
    if (t == 0)  g_count1 = 0;
}

// ---------------------------------------------------------------------------
// Kernel 1: fused distance + label + all large outputs.
// Grid: 512 blocks of 256 threads; 4 pixels/thread (float4).
// Blocks ordered by batch so b=7 runs last (keeps its 32MB slice L2-warm
// for kernel 2).
// ---------------------------------------------------------------------------
__global__ void __launch_bounds__(256) k_main(const float* __restrict__ F,
                                              const float* __restrict__ Cinit,
                                              float* __restrict__ out) {
    __shared__ float sc[2*C];
    int t = threadIdx.x;
    sc[t] = Cinit[t];                 // 256 threads, 256 center values
    __syncthreads();

    int blk = blockIdx.x;             // 0..511
    int b   = blk >> 6;               // 64 blocks per batch image
    int p4  = (blk & 63) * 256 + t;   // float4-pixel index within image, 0..16383
    int n0  = p4 << 2;                // first pixel of the 4

    const float4* Fb = reinterpret_cast<const float4*>(F + (size_t)b * C * NPIX);

    float4 a0 = make_float4(0.f,0.f,0.f,0.f);
    float4 a1 = make_float4(0.f,0.f,0.f,0.f);

    #pragma unroll 8
    for (int ch = 0; ch < C; ch++) {
        float4 f = Fb[ch * (NPIX/4) + p4];
        float c0 = sc[ch];
        float c1 = sc[C + ch];
        a0.x += f.x*c0; a0.y += f.y*c0; a0.z += f.z*c0; a0.w += f.w*c0;
        a1.x += f.x*c1; a1.y += f.y*c1; a1.z += f.z*c1; a1.w += f.w*c1;
    }

    // dists = 0.5*(1 - dot)
    float d0x = 0.5f - 0.5f*a0.x, d1x = 0.5f - 0.5f*a1.x;
    float d0y = 0.5f - 0.5f*a0.y, d1y = 0.5f - 0.5f*a1.y;
    float d0z = 0.5f - 0.5f*a0.z, d1z = 0.5f - 0.5f*a1.z;
    float d0w = 0.5f - 0.5f*a0.w, d1w = 0.5f - 0.5f*a1.w;

    // argmin (first-min tie break -> label 1 only on strict d1 < d0)
    int lx = d1x < d0x;
    int ly = d1y < d0y;
    int lz = d1z < d0z;
    int lw = d1w < d0w;

    float4 lab = make_float4((float)lx, (float)ly, (float)lz, (float)lw);

    // labelsout + labelTinit (identical)
    float4* outL  = reinterpret_cast<float4*>(out + OFF_LABELS + (size_t)b*NPIX + n0);
    float4* outLT = reinterpret_cast<float4*>(out + OFF_LABELT + (size_t)b*NPIX + n0);
    *outL  = lab;
    *outLT = lab;

    // one-hot, interleaved pairs per pixel (raw reshape of [b,N,2])
    float4* outO = reinterpret_cast<float4*>(out + OFF_ONEHOT + (size_t)b*2*NPIX + 2*n0);
    outO[0] = make_float4(1.f - lab.x, lab.x, 1.f - lab.y, lab.y);
    outO[1] = make_float4(1.f - lab.z, lab.z, 1.f - lab.w, lab.w);

    // dist2center, interleaved pairs per pixel
    float4* outD = reinterpret_cast<float4*>(out + OFF_DIST + (size_t)b*2*NPIX + 2*n0);
    outD[0] = make_float4(d0x, d1x, d0y, d1y);
    outD[1] = make_float4(d0z, d1z, d0w, d1w);

    // batch 7: accumulate label==1 count (block reduce -> one atomic)
    if (b == BB - 1) {
        int s = lx + ly + lz + lw;
        #pragma unroll
        for (int o = 16; o > 0; o >>= 1)
            s += __shfl_down_sync(0xffffffffu, s, o);
        __shared__ int ws[8];
        int wid = t >> 5, lid = t & 31;
        if (lid == 0) ws[wid] = s;
        __syncthreads();
        if (wid == 0) {
            int v = (lid < 8) ? ws[lid] : 0;
            #pragma unroll
            for (int o = 4; o > 0; o >>= 1)
                v += __shfl_down_sync(0xffffffffu, v, o);
            if (lid == 0) atomicAdd(&g_count1, v);
        }
    }
}

// ---------------------------------------------------------------------------
// Kernel 2: per-channel masked sums for batch 7.
// Grid: (128 channels, 8 n-tiles), 256 threads, 8 float4/thread.
// Reads labels written by kernel 1 (small, L2-resident across the 128 ch-blocks).
// ---------------------------------------------------------------------------
__global__ void __launch_bounds__(256) k_centers(const float* __restrict__ F,
                                                  const float* __restrict__ out) {
    int ch   = blockIdx.x;
    int tile = blockIdx.y;
    int t    = threadIdx.x;

    const float4* Fp = reinterpret_cast<const float4*>(
        F + ((size_t)(BB-1) * C + ch) * NPIX);
    const float4* Lp = reinterpret_cast<const float4*>(
        out + OFF_LABELS + (size_t)(BB-1) * NPIX);

    float s_all = 0.f, s1 = 0.f;
    int base = tile * (NPIX/8/4);     // 2048 float4 per tile
    #pragma unroll
    for (int i = 0; i < 8; i++) {
        int j = base + i*256 + t;
        float4 f = Fp[j];
        float4 l = Lp[j];
        s_all += f.x + f.y + f.z + f.w;
        s1    += f.x*l.x + f.y*l.y + f.z*l.z + f.w*l.w;
    }

    // block reduce both values
    #pragma unroll
    for (int o = 16; o > 0; o >>= 1) {
        s_all += __shfl_down_sync(0xffffffffu, s_all, o);
        s1    += __shfl_down_sync(0xffffffffu, s1, o);
    }
    __shared__ float wa[8], w1[8];
    int wid = t >> 5, lid = t & 31;
    if (lid == 0) { wa[wid] = s_all; w1[wid] = s1; }
    __syncthreads();
    if (wid == 0) {
        float va = (lid < 8) ? wa[lid] : 0.f;
        float v1 = (lid < 8) ? w1[lid] : 0.f;
        #pragma unroll
        for (int o = 4; o > 0; o >>= 1) {
            va += __shfl_down_sync(0xffffffffu, va, o);
            v1 += __shfl_down_sync(0xffffffffu, v1, o);
        }
        if (lid == 0) {
            atomicAdd(&g_sum[ch],     va - v1);   // label 0 sum
            atomicAdd(&g_sum[C + ch], v1);        // label 1 sum
        }
    }
}

// ---------------------------------------------------------------------------
// Kernel 3: epilogue -> centersIterout [2,128]
// ---------------------------------------------------------------------------
__global__ void k_final(const float* __restrict__ Cinit, float* __restrict__ out) {
    int i = threadIdx.x;              // 0..255, i = k*128+ch
    int k = i >> 7;
    int c1 = g_count1;
    float num = (k ? (float)c1 : (float)(NPIX - c1)) + 1.0f;
    float mean = g_sum[i] / num;
    float ci = Cinit[i];
    out[OFF_CENTERS + i] = ci + 0.001f * (mean - ci);
}

// ---------------------------------------------------------------------------
extern "C" void kernel_launch(void* const* d_in, const int* in_sizes, int n_in,
                              void* d_out, int out_size) {
    const float* F     = (const float*)d_in[0];   // FeatureT [8,128,256,256]
    const float* Cinit = (const float*)d_in[1];   // centerInit [2,128]
    float* out = (float*)d_out;
    (void)in_sizes; (void)n_in; (void)out_size;

    k_zero<<<1, 256>>>();
    k_main<<<512, 256>>>(F, Cinit, out);
    k_centers<<<dim3(C, 8), 256>>>(F, out);
    k_final<<<1, 256>>>(Cinit, out);
}